// round 4
// baseline (speedup 1.0000x reference)
#include <cuda_runtime.h>
#include <cuda_fp16.h>
#include <math.h>
#include <float.h>

// ---------------- problem dims ----------------
#define BB    64
#define NN    1024
#define H16   256
#define H64   1024
#define H128  2048
#define NGATE 8192

#define NCTA_MAX 148
#define USM 13                      // units whose weights live in SMEM
// dynamic SMEM layout for lstm kernel
#define WSM_HALFS   (USM * 4 * 2048)            // 106496 halfs = 212992 B
#define OFF_H       (WSM_HALFS * 2)             // 212992
#define OFF_G       (OFF_H + H128 * 4)          // 221184
#define OFF_C       (OFF_G + 64 * 4)            // 221440
#define LSTM_SMEM   (OFF_C + 16 * 4)            // 221504 B

// ---------------- device scratch ----------------
__device__ __align__(16) float g_x [BB * NN];
__device__ __align__(16) float g_af[BB * H16];
__device__ __align__(16) float g_ai[BB * H64];
__device__ __align__(16) float g_z [BB * H128];
__device__ __align__(16) float g_gi[BB * NGATE];
__device__ __align__(16) float g_part[1 << 21];     // split-K partials (8MB)
__device__ __align__(16) float g_h [2][H128];
__device__ unsigned g_slot[NCTA_MAX * 8];

__global__ void reset_kernel() {
    for (int i = threadIdx.x; i < NCTA_MAX * 8; i += blockDim.x) g_slot[i] = 0u;
}

// ---------------- GCN: one block per sample ----------------
__global__ __launch_bounds__(1024) void gcn_kernel(
    const float* __restrict__ inp,
    const float* __restrict__ gc1w, const float* __restrict__ gc1b,
    const float* __restrict__ gc2w, const float* __restrict__ gc2b)
{
    __shared__ float xs[NN];
    __shared__ float s2[NN];
    const int s = blockIdx.x;
    const int i = threadIdx.x;
    xs[i] = inp[s * NN + i];
    __syncthreads();
    const float xi = xs[i];

    float d0 = INFINITY, d1 = INFINITY, d2 = INFINITY, d3 = INFINITY;
    int i0 = 0, i1 = 0, i2 = 0, i3 = 0;
#pragma unroll 4
    for (int j = 0; j < NN; ++j) {
        float dj = fabsf(xi - xs[j]);
        if (j != i && dj < d3) {
            if (dj < d2) {
                d3 = d2; i3 = i2;
                if (dj < d1) {
                    d2 = d1; i2 = i1;
                    if (dj < d0) { d1 = d0; i1 = i0; d0 = dj; i0 = j; }
                    else         { d1 = dj; i1 = j; }
                } else { d2 = dj; i2 = j; }
            } else { d3 = dj; i3 = j; }
        }
    }

    float S = xs[i0] + xs[i1] + xs[i2] + xs[i3];
    float v = 0.f;
#pragma unroll
    for (int c = 0; c < 4; ++c) {
        float hc = fmaxf(gc1w[c] * S + gc1b[c], 0.f);
        v += hc * gc2w[c];
    }
    s2[i] = v;
    __syncthreads();
    g_x[s * NN + i] = s2[i0] + s2[i1] + s2[i2] + s2[i3] + gc2b[0];
}

// ---------------- small split-K GEMM (64xR', 128 thr) for fl/il ----------------
template <int R, int J, int KC>
__global__ __launch_bounds__(128) void gemm_sk(
    const float* __restrict__ A, const float* __restrict__ W, float* __restrict__ part)
{
    __shared__ float As[64][33];
    __shared__ float Ws[32][33];
    const int JC  = J / KC;
    const int kc  = blockIdx.y;
    const int br0 = blockIdx.x * 32;
    const int tid = threadIdx.x;
    const int tq  = tid & 15;
    const int rq  = tid >> 4;

    float acc[4][4];
#pragma unroll
    for (int a = 0; a < 4; ++a)
#pragma unroll
        for (int b = 0; b < 4; ++b) acc[a][b] = 0.f;

    const int j_end = (kc + 1) * JC;
    for (int j0 = kc * JC; j0 < j_end; j0 += 32) {
        for (int idx = tid; idx < 64 * 32; idx += 128) {
            int row = idx >> 5, col = idx & 31;
            As[row][col] = A[row * J + j0 + col];
        }
        for (int idx = tid; idx < 32 * 32; idx += 128) {
            int row = idx >> 5, col = idx & 31;
            Ws[row][col] = W[(size_t)(br0 + row) * J + j0 + col];
        }
        __syncthreads();
#pragma unroll
        for (int kk = 0; kk < 32; ++kk) {
            float av[4], wv[4];
#pragma unroll
            for (int a = 0; a < 4; ++a) av[a] = As[tq + 16 * a][kk];
#pragma unroll
            for (int b = 0; b < 4; ++b) wv[b] = Ws[rq + 8 * b][kk];
#pragma unroll
            for (int a = 0; a < 4; ++a)
#pragma unroll
                for (int b = 0; b < 4; ++b) acc[a][b] += av[a] * wv[b];
        }
        __syncthreads();
    }
#pragma unroll
    for (int a = 0; a < 4; ++a)
#pragma unroll
        for (int b = 0; b < 4; ++b)
            part[(size_t)kc * 64 * R + (tq + 16 * a) * R + br0 + rq + 8 * b] = acc[a][b];
}

// ---------------- big split-K GEMM: 64x64 tile, 256 thr, double-buffered ----------------
template <int R, int J, int KC>
__global__ __launch_bounds__(256) void gemm64(
    const float* __restrict__ A, const float* __restrict__ W, float* __restrict__ part)
{
    __shared__ float As[2][64][33];
    __shared__ float Ws[2][64][33];
    const int JC  = J / KC;
    const int kc  = blockIdx.y;
    const int br0 = blockIdx.x * 64;
    const int tid = threadIdx.x;
    const int tq  = tid & 15;
    const int rq  = tid >> 4;      // 0..15

    float acc[4][4];
#pragma unroll
    for (int a = 0; a < 4; ++a)
#pragma unroll
        for (int b = 0; b < 4; ++b) acc[a][b] = 0.f;

    const int jbeg = kc * JC;
    const int nit  = JC / 32;

    auto load = [&](int s, int j0) {
#pragma unroll
        for (int idx = tid; idx < 64 * 32; idx += 256) {
            int row = idx >> 5, col = idx & 31;
            As[s][row][col] = A[row * J + j0 + col];
            Ws[s][row][col] = W[(size_t)(br0 + row) * J + j0 + col];
        }
    };

    load(0, jbeg);
    __syncthreads();
    for (int it = 0; it < nit; ++it) {
        int s = it & 1;
        if (it + 1 < nit) load(s ^ 1, jbeg + (it + 1) * 32);
#pragma unroll
        for (int kk = 0; kk < 32; ++kk) {
            float av[4], wv[4];
#pragma unroll
            for (int a = 0; a < 4; ++a) av[a] = As[s][tq + 16 * a][kk];
#pragma unroll
            for (int b = 0; b < 4; ++b) wv[b] = Ws[s][rq + 16 * b][kk];
#pragma unroll
            for (int a = 0; a < 4; ++a)
#pragma unroll
                for (int b = 0; b < 4; ++b) acc[a][b] += av[a] * wv[b];
        }
        __syncthreads();
    }
#pragma unroll
    for (int a = 0; a < 4; ++a)
#pragma unroll
        for (int b = 0; b < 4; ++b)
            part[(size_t)kc * 64 * R + (tq + 16 * a) * R + br0 + rq + 16 * b] = acc[a][b];
}

// ---------------- reduce partials ----------------
template <int R, int KC, bool RELU, bool HASB2>
__global__ __launch_bounds__(256) void reduce_k(
    const float* __restrict__ part,
    const float* __restrict__ b1, const float* __restrict__ b2,
    float* __restrict__ C)
{
    int i = blockIdx.x * 256 + threadIdx.x;
    if (i >= 64 * R) return;
    int r = i % R;
    float s = 0.f;
#pragma unroll
    for (int kc = 0; kc < KC; ++kc) s += part[(size_t)kc * 64 * R + i];
    s += b1[r];
    if (HASB2) s += b2[r];
    if (RELU) s = fmaxf(s, 0.f);
    C[i] = s;
}

__device__ __forceinline__ float sigmoidf_(float x) { return 1.f / (1.f + expf(-x)); }

// ---------------- persistent LSTM, SMEM-resident fp16 weights ----------------
__global__ __launch_bounds__(1024, 1) void lstm_kernel(
    const float* __restrict__ w_hh, float* __restrict__ out, int ncta)
{
    extern __shared__ unsigned char smraw[];
    __half*  w_sm = (__half*)smraw;                 // [min(nu,USM)*4][2048]
    float*   h_sm = (float*)(smraw + OFF_H);        // [2048]
    float*   g_sm = (float*)(smraw + OFF_G);        // [64]
    float*   c_sm = (float*)(smraw + OFF_C);        // [16]

    const int tid  = threadIdx.x;
    const int bid  = blockIdx.x;
    const int warp = tid >> 5, lane = tid & 31;

    const int base = H128 / ncta;
    const int rem  = H128 - base * ncta;
    const int nu   = (bid < rem) ? base + 1 : base;    // 13 or 14 (ncta=148)
    const int u0   = bid * base + min(bid, rem);
    const int usm  = (nu < USM) ? nu : USM;            // units in SMEM
    const int nrows = 4 * nu;

    // -------- prologue: convert this CTA's SMEM units fp32 -> fp16 --------
    {
        const int tot2 = usm * 4 * 1024;               // float2 per CTA
        __half2* dst = (__half2*)w_sm;
        for (int idx = tid; idx < tot2; idx += 1024) {
            int sr = idx >> 10;                        // local row, 1024 float2/row
            int c2 = idx & 1023;
            int g  = sr / usm, ui = sr - g * usm;
            const float2* src = (const float2*)(w_hh + (size_t)(g * H128 + u0 + ui) * H128);
            float2 v = src[c2];
            dst[idx] = __floats2half2_rn(v.x, v.y);
        }
    }

    // per-warp row assignments: lr = warp + 32k
    int cnt = 0;
    int rowg[2];            // global gate row (for g_gi)
    int gsl [2];            // g_sm slot = lr
    int wsr [2];            // SMEM row index or -1
    const float4* wf4[2];   // fp32 global row (if not in SMEM)
#pragma unroll
    for (int k = 0; k < 2; ++k) {
        int lr = warp + 32 * k;
        if (lr < nrows) {
            int g = lr / nu, ui = lr - g * nu;
            rowg[cnt] = g * H128 + u0 + ui;
            gsl [cnt] = lr;
            if (ui < usm) { wsr[cnt] = g * usm + ui; wf4[cnt] = nullptr; }
            else          { wsr[cnt] = -1; wf4[cnt] = (const float4*)(w_hh + (size_t)rowg[cnt] * H128); }
            ++cnt;
        }
    }

    volatile unsigned* slots = (volatile unsigned*)g_slot;

    if (tid < nu) { c_sm[tid] = 0.f; g_h[0][u0 + tid] = 0.f; }
    __syncthreads();
    if (tid == 0) { __threadfence(); slots[bid * 8] = 1u; }
    if (tid < ncta) { while (slots[tid * 8] < 1u) {} }
    __threadfence();
    __syncthreads();

    const float4* hs4 = (const float4*)h_sm;

    for (int t = 0; t < BB; ++t) {
        const float4* hb = (const float4*)g_h[t & 1];
        if (tid < H128 / 4) ((float4*)h_sm)[tid] = __ldcg(hb + tid);
        __syncthreads();

        float acc[2] = {0.f, 0.f};
#pragma unroll
        for (int k = 0; k < 2; ++k) {
            if (k >= cnt) break;
            if (wsr[k] >= 0) {
                const uint4* wr = (const uint4*)(w_sm + (size_t)wsr[k] * H128);
#pragma unroll
                for (int i = 0; i < 8; ++i) {
                    int o = lane + 32 * i;
                    uint4 w4 = wr[o];
                    float4 ha = hs4[2 * o], hb4 = hs4[2 * o + 1];
                    const __half2* hp = (const __half2*)&w4;
                    float2 f;
                    f = __half22float2(hp[0]); acc[k] += f.x * ha.x  + f.y * ha.y;
                    f = __half22float2(hp[1]); acc[k] += f.x * ha.z  + f.y * ha.w;
                    f = __half22float2(hp[2]); acc[k] += f.x * hb4.x + f.y * hb4.y;
                    f = __half22float2(hp[3]); acc[k] += f.x * hb4.z + f.y * hb4.w;
                }
            } else {
                const float4* wr = wf4[k];
#pragma unroll
                for (int i = 0; i < 16; ++i) {
                    int o = lane + 32 * i;
                    float4 w4 = __ldg(wr + o);
                    float4 h4 = hs4[o];
                    acc[k] += w4.x * h4.x + w4.y * h4.y + w4.z * h4.z + w4.w * h4.w;
                }
            }
        }
#pragma unroll
        for (int k = 0; k < 2; ++k)
#pragma unroll
            for (int o = 16; o > 0; o >>= 1) acc[k] += __shfl_xor_sync(0xffffffffu, acc[k], o);
        if (lane == 0) {
#pragma unroll
            for (int k = 0; k < 2; ++k)
                if (k < cnt) g_sm[gsl[k]] = acc[k] + g_gi[t * NGATE + rowg[k]];
        }
        __syncthreads();

        if (tid < nu) {
            float ig = g_sm[tid], fg = g_sm[nu + tid], gg = g_sm[2 * nu + tid], og = g_sm[3 * nu + tid];
            float c = sigmoidf_(fg) * c_sm[tid] + sigmoidf_(ig) * tanhf(gg);
            float h = sigmoidf_(og) * tanhf(c);
            c_sm[tid] = c;
            g_h[(t + 1) & 1][u0 + tid] = h;
            out[t * H128 + u0 + tid] = h;
        }
        __syncthreads();
        if (tid == 0) { __threadfence(); slots[bid * 8] = (unsigned)(t + 2); }
        if (tid < ncta) { while (slots[tid * 8] < (unsigned)(t + 2)) {} }
        __threadfence();
        __syncthreads();
    }
}

// ---------------- launch ----------------
extern "C" void kernel_launch(void* const* d_in, const int* in_sizes, int n_in,
                              void* d_out, int out_size)
{
    const float* inp  = (const float*)d_in[0];
    const float* gc1w = (const float*)d_in[3];
    const float* gc1b = (const float*)d_in[4];
    const float* gc2w = (const float*)d_in[5];
    const float* gc2b = (const float*)d_in[6];
    const float* flw  = (const float*)d_in[7];
    const float* flb  = (const float*)d_in[8];
    const float* ilw  = (const float*)d_in[9];
    const float* ilb  = (const float*)d_in[10];
    const float* olw  = (const float*)d_in[11];
    const float* olb  = (const float*)d_in[12];
    const float* wih  = (const float*)d_in[13];
    const float* whh  = (const float*)d_in[14];
    const float* bih  = (const float*)d_in[15];
    const float* bhh  = (const float*)d_in[16];
    float* out = (float*)d_out;

    void *px, *paf, *pai, *pz, *pgi, *ppart;
    cudaGetSymbolAddress(&px,    g_x);
    cudaGetSymbolAddress(&paf,   g_af);
    cudaGetSymbolAddress(&pai,   g_ai);
    cudaGetSymbolAddress(&pz,    g_z);
    cudaGetSymbolAddress(&pgi,   g_gi);
    cudaGetSymbolAddress(&ppart, g_part);
    float* part = (float*)ppart;

    int sms = 0;
    cudaDeviceGetAttribute(&sms, cudaDevAttrMultiProcessorCount, 0);
    int ncta = sms;
    if (ncta > NCTA_MAX) ncta = NCTA_MAX;
    if (ncta < 128) ncta = 128;

    cudaFuncSetAttribute(lstm_kernel, cudaFuncAttributeMaxDynamicSharedMemorySize, LSTM_SMEM);

    reset_kernel<<<1, 256>>>();
    gcn_kernel<<<BB, NN>>>(inp, gc1w, gc1b, gc2w, gc2b);

    // fl: [64,256] = x @ fl_w.T ; relu
    gemm_sk<H16, NN, 16><<<dim3(H16 / 32, 16), 128>>>((const float*)px, flw, part);
    reduce_k<H16, 16, true, false><<<(64 * H16 + 255) / 256, 256>>>(part, flb, nullptr, (float*)paf);
    // il: [64,1024] = af @ il_w.T ; relu
    gemm_sk<H64, H16, 4><<<dim3(H64 / 32, 4), 128>>>((const float*)paf, ilw, part);
    reduce_k<H64, 4, true, false><<<(64 * H64 + 255) / 256, 256>>>(part, ilb, nullptr, (float*)pai);
    // ol: [64,2048] = ai @ ol_w.T ; relu -> z
    gemm64<H128, H64, 4><<<dim3(H128 / 64, 4), 256>>>((const float*)pai, olw, part);
    reduce_k<H128, 4, true, false><<<(64 * H128 + 255) / 256, 256>>>(part, olb, nullptr, (float*)pz);
    // gate: [64,8192] = z @ w_ih.T + b_ih + b_hh
    gemm64<NGATE, H128, 4><<<dim3(NGATE / 64, 4), 256>>>((const float*)pz, wih, part);
    reduce_k<NGATE, 4, false, true><<<(64 * NGATE + 255) / 256, 256>>>(part, bih, bhh, (float*)pgi);

    lstm_kernel<<<ncta, 1024, LSTM_SMEM>>>(whh, out, ncta);
}